// round 5
// baseline (speedup 1.0000x reference)
#include <cuda_runtime.h>
#include <cuda_bf16.h>

#define PDIM 1024
#define MDIM 64
#define RDIM 32
#define TI   4        // rows per block
#define NTH  256      // threads per block (64 per row)

__device__ float d_hi[PDIM];
__device__ float d_nei[PDIM];

// Prolog: hi[i] = h[i]·w_hi, nei[j] = h[j]·w_nei
__global__ void prep_kernel(const float* __restrict__ h,
                            const float* __restrict__ W_att) {
    int idx = blockIdx.x * blockDim.x + threadIdx.x;   // 0..2047
    if (idx >= 2 * PDIM) return;
    int row = idx & (PDIM - 1);
    const float* w  = W_att + RDIM + ((idx < PDIM) ? 0 : MDIM);
    const float* hr = h + row * MDIM;
    float s = 0.f;
#pragma unroll
    for (int m2 = 0; m2 < MDIM; m2++) s = fmaf(hr[m2], w[m2], s);
    if (idx < PDIM) d_hi[row] = s; else d_nei[row] = s;
}

__global__ __launch_bounds__(NTH) void social_kernel(
    const float* __restrict__ h,
    const float* __restrict__ corr,
    const int*   __restrict__ nei,
    const float* __restrict__ W_rela,
    const float* __restrict__ b_rela,
    const float* __restrict__ W_att,
    const float* __restrict__ b_att,
    float*       __restrict__ out)
{
    __shared__ float sW0[RDIM], sW1[RDIM], sbr[RDIM], swr[RDIM];
    __shared__ float snei[PDIM];
    __shared__ float swj[PDIM * TI];     // weights, j-major: [j][li]
    __shared__ float sredA[8];
    __shared__ float sredB[8];
    __shared__ float spart[TI * NTH];    // [g][li][m]

    const int tid = threadIdx.x;
    const int li  = tid >> 6;            // row within tile, 0..3
    const int lt  = tid & 63;            // lane within row, 0..63
    const int iglob = blockIdx.x * TI + li;

    if (tid < RDIM) {
        sW0[tid] = W_rela[tid];
        sW1[tid] = W_rela[RDIM + tid];
        sbr[tid] = b_rela[tid];
        swr[tid] = W_att[tid];
    }
    for (int j = tid; j < PDIM; j += NTH) snei[j] = d_nei[j];
    __syncthreads();

    const float bias = d_hi[iglob] + b_att[0];
    const float2* crow = reinterpret_cast<const float2*>(corr) + (size_t)iglob * PDIM;
    const int*    nrow = nei + (size_t)iglob * PDIM;

    // ---- pass 1: scores for this row's 16 j's per thread ----
    float2 c[16];
    unsigned mbits = 0;
#pragma unroll
    for (int k = 0; k < 16; k++) {
        int j = lt + k * 64;
        c[k] = crow[j];
        if (nrow[j] > 0) mbits |= 1u << k;
    }

    float s[16];
#pragma unroll
    for (int k = 0; k < 16; k++) s[k] = 0.f;

#pragma unroll
    for (int r = 0; r < RDIM; r++) {
        const float A = sW0[r], B = sW1[r], Cb = sbr[r], Wr = swr[r];
#pragma unroll
        for (int k = 0; k < 16; k++) {
            float re = fmaf(c[k].x, A, fmaf(c[k].y, B, Cb));
            re = fmaxf(re, 0.f);
            s[k] = fmaf(re, Wr, s[k]);
        }
    }

    float lmax = -1e30f;
#pragma unroll
    for (int k = 0; k < 16; k++) {
        int j = lt + k * 64;
        float v = s[k] + bias + snei[j];
        v = (mbits >> k & 1u) ? v : 0.f;     // masked -> 0
        if (v == 0.f) v = -1e-6f;            // exact reference semantics
        s[k] = v;
        lmax = fmaxf(lmax, v);
    }

    // ---- row softmax over 64 threads (warps 2li, 2li+1) ----
#pragma unroll
    for (int o = 16; o > 0; o >>= 1)
        lmax = fmaxf(lmax, __shfl_xor_sync(0xffffffffu, lmax, o));
    if ((tid & 31) == 0) sredA[tid >> 5] = lmax;
    __syncthreads();
    const float rmax = fmaxf(sredA[2 * li], sredA[2 * li + 1]);

    float lsum = 0.f;
#pragma unroll
    for (int k = 0; k < 16; k++) {
        float e = __expf(s[k] - rmax);
        s[k] = e;
        lsum += e;
    }
#pragma unroll
    for (int o = 16; o > 0; o >>= 1)
        lsum += __shfl_xor_sync(0xffffffffu, lsum, o);
    if ((tid & 31) == 0) sredB[tid >> 5] = lsum;
    __syncthreads();
    const float inv = 1.0f / (sredB[2 * li] + sredB[2 * li + 1]);

#pragma unroll
    for (int k = 0; k < 16; k++) {
        int j = lt + k * 64;
        swj[j * TI + li] = (mbits >> k & 1u) ? s[k] * inv : 0.f;
    }
    __syncthreads();

    // ---- pass 2: out[li] = sum_j w[li][j] * h[j][m] ----
    const int m = tid & 63;
    const int g = tid >> 6;                  // j-chunk, 0..3
    float a0 = 0.f, a1 = 0.f, a2 = 0.f, a3 = 0.f;
    const float4* wv = reinterpret_cast<const float4*>(swj) + g * 256;
    const float*  hp = h + (size_t)(g * 256) * MDIM + m;
#pragma unroll 4
    for (int jj = 0; jj < 256; jj++) {
        float4 w4 = wv[jj];                  // broadcast LDS.128: all 4 rows' weights
        float  hv = hp[(size_t)jj * MDIM];   // coalesced across m
        a0 = fmaf(w4.x, hv, a0);
        a1 = fmaf(w4.y, hv, a1);
        a2 = fmaf(w4.z, hv, a2);
        a3 = fmaf(w4.w, hv, a3);
    }
    spart[g * NTH + 0 * 64 + m] = a0;
    spart[g * NTH + 1 * 64 + m] = a1;
    spart[g * NTH + 2 * 64 + m] = a2;
    spart[g * NTH + 3 * 64 + m] = a3;
    __syncthreads();

    float o = spart[tid] + spart[NTH + tid] + spart[2 * NTH + tid] + spart[3 * NTH + tid];
    out[(size_t)blockIdx.x * TI * MDIM + tid] = o;
}

extern "C" void kernel_launch(void* const* d_in, const int* in_sizes, int n_in,
                              void* d_out, int out_size) {
    const float* h      = (const float*)d_in[0];
    const float* corr   = (const float*)d_in[1];
    const int*   nei    = (const int*)d_in[2];
    const float* W_rela = (const float*)d_in[3];
    const float* b_rela = (const float*)d_in[4];
    const float* W_att  = (const float*)d_in[5];
    const float* b_att  = (const float*)d_in[6];
    float* out = (float*)d_out;

    prep_kernel<<<(2 * PDIM + 255) / 256, 256>>>(h, W_att);
    social_kernel<<<PDIM / TI, NTH>>>(h, corr, nei, W_rela, b_rela, W_att, b_att, out);
}

// round 7
// speedup vs baseline: 1.0487x; 1.0487x over previous
#include <cuda_runtime.h>
#include <cuda_bf16.h>

#define PDIM 1024
#define MDIM 64
#define RDIM 32
#define TI   4        // rows per block
#define NTH  512      // threads per block (128 per row)

__device__ float d_hi[PDIM];
__device__ float d_nei[PDIM];

// Prolog: hi[i] = h[i]·w_hi, nei[j] = h[j]·w_nei
__global__ void prep_kernel(const float* __restrict__ h,
                            const float* __restrict__ W_att) {
    int idx = blockIdx.x * blockDim.x + threadIdx.x;   // 0..2047
    if (idx >= 2 * PDIM) return;
    int row = idx & (PDIM - 1);
    const float* w  = W_att + RDIM + ((idx < PDIM) ? 0 : MDIM);
    const float* hr = h + row * MDIM;
    float s = 0.f;
#pragma unroll
    for (int m2 = 0; m2 < MDIM; m2++) s = fmaf(hr[m2], w[m2], s);
    if (idx < PDIM) d_hi[row] = s; else d_nei[row] = s;
}

__global__ __launch_bounds__(NTH, 2) void social_kernel(
    const float* __restrict__ h,
    const float* __restrict__ corr,
    const int*   __restrict__ nei,
    const float* __restrict__ W_rela,
    const float* __restrict__ b_rela,
    const float* __restrict__ W_att,
    const float* __restrict__ b_att,
    float*       __restrict__ out)
{
    __shared__ float sW0[RDIM], sW1[RDIM], sbr[RDIM], swr[RDIM];
    __shared__ float snei[PDIM];
    __shared__ float swj[PDIM * TI];     // weights, j-major: [j][li]
    __shared__ float sredA[16];          // [row][warp-in-row]
    __shared__ float sredB[16];
    __shared__ float spart[8 * 256];     // [g][row][m]

    const int tid = threadIdx.x;
    const int li  = tid >> 7;            // row within tile, 0..3
    const int lt  = tid & 127;           // lane within row, 0..127
    const int iglob = blockIdx.x * TI + li;

    if (tid < RDIM) {
        sW0[tid] = W_rela[tid];
        sW1[tid] = W_rela[RDIM + tid];
        sbr[tid] = b_rela[tid];
        swr[tid] = W_att[tid];
    }
    for (int j = tid; j < PDIM; j += NTH) snei[j] = d_nei[j];
    __syncthreads();

    const float bias = d_hi[iglob] + b_att[0];
    const int jbase = lt * 8;            // 8 contiguous j's per thread

    // ---- pass 1: load corr (float4) + nei (int4) for 8 j's ----
    const float4* crow4 = reinterpret_cast<const float4*>(corr + (size_t)iglob * PDIM * 2) + lt * 4;
    const int4*   nrow4 = reinterpret_cast<const int4*>(nei + (size_t)iglob * PDIM) + lt * 2;

    float4 cv[4];
    int4   nv[2];
#pragma unroll
    for (int t = 0; t < 4; t++) cv[t] = crow4[t];
#pragma unroll
    for (int t = 0; t < 2; t++) nv[t] = nrow4[t];

    float cx[8], cy[8];
#pragma unroll
    for (int t = 0; t < 4; t++) {
        cx[2*t]   = cv[t].x;  cy[2*t]   = cv[t].y;
        cx[2*t+1] = cv[t].z;  cy[2*t+1] = cv[t].w;
    }
    unsigned mbits = 0;
    {
        const int* ni = reinterpret_cast<const int*>(nv);
#pragma unroll
        for (int k = 0; k < 8; k++) if (ni[k] > 0) mbits |= 1u << k;
    }

    float s[8];
#pragma unroll
    for (int k = 0; k < 8; k++) s[k] = 0.f;

#pragma unroll
    for (int r = 0; r < RDIM; r++) {
        const float A = sW0[r], B = sW1[r], Cb = sbr[r], Wr = swr[r];
#pragma unroll
        for (int k = 0; k < 8; k++) {
            float re = fmaf(cx[k], A, fmaf(cy[k], B, Cb));
            re = fmaxf(re, 0.f);
            s[k] = fmaf(re, Wr, s[k]);
        }
    }

    float lmax = -1e30f;
#pragma unroll
    for (int k = 0; k < 8; k++) {
        float v = s[k] + bias + snei[jbase + k];
        v = (mbits >> k & 1u) ? v : 0.f;     // masked -> 0
        if (v == 0.f) v = -1e-6f;            // exact reference semantics
        s[k] = v;
        lmax = fmaxf(lmax, v);
    }

    // ---- row softmax: 128 threads = 4 warps per row ----
#pragma unroll
    for (int o = 16; o > 0; o >>= 1)
        lmax = fmaxf(lmax, __shfl_xor_sync(0xffffffffu, lmax, o));
    if ((tid & 31) == 0) sredA[tid >> 5] = lmax;   // [li*4 + warp-in-row]
    __syncthreads();
    const float rmax = fmaxf(fmaxf(sredA[li*4+0], sredA[li*4+1]),
                             fmaxf(sredA[li*4+2], sredA[li*4+3]));

    float lsum = 0.f;
#pragma unroll
    for (int k = 0; k < 8; k++) {
        float e = __expf(s[k] - rmax);
        s[k] = e;
        lsum += e;
    }
#pragma unroll
    for (int o = 16; o > 0; o >>= 1)
        lsum += __shfl_xor_sync(0xffffffffu, lsum, o);
    if ((tid & 31) == 0) sredB[tid >> 5] = lsum;
    __syncthreads();
    const float inv = 1.0f / (sredB[li*4+0] + sredB[li*4+1] +
                              sredB[li*4+2] + sredB[li*4+3]);

#pragma unroll
    for (int k = 0; k < 8; k++) {
        swj[(jbase + k) * TI + li] = (mbits >> k & 1u) ? s[k] * inv : 0.f;
    }
    __syncthreads();

    // ---- pass 2: out[row][m] = sum_j w[row][j] * h[j][m], 8-way j split ----
    const int m = tid & 63;
    const int g = tid >> 6;                  // j-chunk, 0..7 (128 j's each)
    float a0 = 0.f, a1 = 0.f, a2 = 0.f, a3 = 0.f;
    const float4* wv = reinterpret_cast<const float4*>(swj) + g * 128;
    const float*  hp = h + (size_t)(g * 128) * MDIM + m;
#pragma unroll 4
    for (int jj = 0; jj < 128; jj++) {
        float4 w4 = wv[jj];                  // broadcast LDS.128: 4 rows' weights
        float  hv = hp[(size_t)jj * MDIM];   // coalesced across m
        a0 = fmaf(w4.x, hv, a0);
        a1 = fmaf(w4.y, hv, a1);
        a2 = fmaf(w4.z, hv, a2);
        a3 = fmaf(w4.w, hv, a3);
    }
    spart[g * 256 + 0 * 64 + m] = a0;
    spart[g * 256 + 1 * 64 + m] = a1;
    spart[g * 256 + 2 * 64 + m] = a2;
    spart[g * 256 + 3 * 64 + m] = a3;
    __syncthreads();

    if (tid < 256) {
        float o = 0.f;
#pragma unroll
        for (int gg = 0; gg < 8; gg++) o += spart[gg * 256 + tid];
        out[(size_t)blockIdx.x * TI * MDIM + tid] = o;
    }
}

extern "C" void kernel_launch(void* const* d_in, const int* in_sizes, int n_in,
                              void* d_out, int out_size) {
    const float* h      = (const float*)d_in[0];
    const float* corr   = (const float*)d_in[1];
    const int*   nei    = (const int*)d_in[2];
    const float* W_rela = (const float*)d_in[3];
    const float* b_rela = (const float*)d_in[4];
    const float* W_att  = (const float*)d_in[5];
    const float* b_att  = (const float*)d_in[6];
    float* out = (float*)d_out;

    prep_kernel<<<(2 * PDIM + 255) / 256, 256>>>(h, W_att);
    social_kernel<<<PDIM / TI, NTH>>>(h, corr, nei, W_rela, b_rela, W_att, b_att, out);
}